// round 3
// baseline (speedup 1.0000x reference)
#include <cuda_runtime.h>

// Problem constants (fixed by setup_inputs)
#define BB 16
#define HH 2048
#define WW 2048
#define SS 5000
#define NST (BB * SS)          // 80000 stations

#define THREADS 256
#define NBLK ((NST + THREADS - 1) / THREADS)   // 313

// Scratch for deterministic single-kernel reduction (no device mallocs allowed)
__device__ float g_partials[NBLK];
__device__ int   g_count = 0;   // self-resetting block-completion counter

__global__ __launch_bounds__(THREADS)
void station_loss_fused_kernel(const float* __restrict__ pred,
                               const int*   __restrict__ pos,
                               const float* __restrict__ runoff,
                               float*       __restrict__ out)
{
    const int tid = blockIdx.x * blockDim.x + threadIdx.x;

    float per_station = 0.0f;
    if (tid < NST) {
        const int b = tid / SS;
        const int2 pxy = __ldg((const int2*)pos + tid);  // .x = px (width), .y = py (height)
        const int px = pxy.x;
        const int py = pxy.y;
        const float* __restrict__ p = pred + (long long)b * (HH * WW);

        // Issue all 9 loads with clamped (always-valid) addresses so ptxas can
        // front-batch them (max MLP); mask invalid taps arithmetically.
        float vals[9];
        float flags[9];
        #pragma unroll
        for (int dy = -1; dy <= 1; dy++) {
            #pragma unroll
            for (int dx = -1; dx <= 1; dx++) {
                const int i = (dy + 1) * 3 + (dx + 1);
                const int y = py + dy;
                const int x = px + dx;
                const bool v = (y >= 0) & (y < HH) & (x >= 0) & (x < WW);
                const int yc = min(max(y, 0), HH - 1);
                const int xc = min(max(x, 0), WW - 1);
                vals[i]  = __ldg(p + yc * WW + xc);
                flags[i] = v ? 1.0f : 0.0f;
            }
        }

        float sum = 0.0f, cnt = 0.0f;
        #pragma unroll
        for (int i = 0; i < 9; i++) {
            sum += vals[i] * flags[i];
            cnt += flags[i];
        }
        const float avg  = sum / cnt;
        const float diff = avg - runoff[tid];
        per_station = diff * diff;
    }

    // Deterministic block reduction: warp shuffle then shared-mem tree.
    __shared__ float smem[THREADS / 32];
    __shared__ bool  s_is_last;
    float v = per_station;
    #pragma unroll
    for (int off = 16; off > 0; off >>= 1)
        v += __shfl_down_sync(0xFFFFFFFFu, v, off);
    const int lane = threadIdx.x & 31;
    const int warp = threadIdx.x >> 5;
    if (lane == 0) smem[warp] = v;
    __syncthreads();
    if (warp == 0) {
        v = (lane < THREADS / 32) ? smem[lane] : 0.0f;
        #pragma unroll
        for (int off = 16; off > 0; off >>= 1)
            v += __shfl_down_sync(0xFFFFFFFFu, v, off);
        if (lane == 0) {
            g_partials[blockIdx.x] = v;
            __threadfence();
            const int done = atomicAdd(&g_count, 1);
            s_is_last = (done == NBLK - 1);
        }
    }
    __syncthreads();

    // Last block to finish reduces all partials in a FIXED order -> deterministic.
    if (s_is_last) {
        __threadfence();
        float s = 0.0f;
        for (int i = threadIdx.x; i < NBLK; i += THREADS)
            s += g_partials[i];
        #pragma unroll
        for (int off = 16; off > 0; off >>= 1)
            s += __shfl_down_sync(0xFFFFFFFFu, s, off);
        if (lane == 0) smem[warp] = s;
        __syncthreads();
        if (warp == 0) {
            s = (lane < THREADS / 32) ? smem[lane] : 0.0f;
            #pragma unroll
            for (int off = 16; off > 0; off >>= 1)
                s += __shfl_down_sync(0xFFFFFFFFu, s, off);
            if (lane == 0) {
                out[0] = s / (float)NST;
                g_count = 0;   // reset for next graph replay
            }
        }
    }
}

extern "C" void kernel_launch(void* const* d_in, const int* in_sizes, int n_in,
                              void* d_out, int out_size)
{
    const float* pred   = (const float*)d_in[0];  // (16,1,2048,2048) f32
    const int*   pos    = (const int*)  d_in[1];  // (16,5000,2) i32
    const float* runoff = (const float*)d_in[2];  // (16,5000) f32
    float* out = (float*)d_out;

    station_loss_fused_kernel<<<NBLK, THREADS>>>(pred, pos, runoff, out);
}

// round 4
// speedup vs baseline: 1.2694x; 1.2694x over previous
#include <cuda_runtime.h>

// Problem constants (fixed by setup_inputs)
#define BB 16
#define HH 2048
#define WW 2048
#define SS 5000
#define NST (BB * SS)          // 80000 stations

#define THREADS 256
#define NBLK ((NST + THREADS - 1) / THREADS)   // 313

// Scratch for deterministic two-stage reduction (no device mallocs allowed)
__device__ float g_partials[NBLK];

// Select element r (0..3) from the 4-float window {a.x, a.y, b.x, b.y}.
__device__ __forceinline__ float sel4(float2 a, float2 b, int r)
{
    const float lo = (r & 1) ? a.y : a.x;
    const float hi = (r & 1) ? b.y : b.x;
    return (r & 2) ? hi : lo;
}

__global__ __launch_bounds__(THREADS)
void station_loss_kernel(const float* __restrict__ pred,
                         const int*   __restrict__ pos,
                         const float* __restrict__ runoff)
{
    const int tid = blockIdx.x * blockDim.x + threadIdx.x;

    float per_station = 0.0f;
    if (tid < NST) {
        const int b = tid / SS;
        const int2 pxy = __ldg((const int2*)pos + tid);  // .x = px (width), .y = py (height)
        const int x = pxy.x;
        const int y = pxy.y;
        const float* __restrict__ p = pred + (long long)b * (HH * WW);

        // Column window: two float2 loads starting at even xa cover
        // {clamp(x-1), x, clamp(x+1)} (interior: x-1-xa in {0,1} => x+1 <= xa+3).
        int xa = max(x - 1, 0);
        xa = min(xa, WW - 4);
        xa &= ~1;

        const int ym1 = max(y - 1, 0);
        const int yp1 = min(y + 1, HH - 1);

        const float* r0 = p + ym1 * WW + xa;
        const float* r1 = p + y   * WW + xa;
        const float* r2 = p + yp1 * WW + xa;

        // Front-batch all 7 loads for max MLP.
        const float2 a0 = __ldg((const float2*)(r0));
        const float2 b0 = __ldg((const float2*)(r0 + 2));
        const float2 a1 = __ldg((const float2*)(r1));
        const float2 b1 = __ldg((const float2*)(r1 + 2));
        const float2 a2 = __ldg((const float2*)(r2));
        const float2 b2 = __ldg((const float2*)(r2 + 2));
        const float  ro = __ldg(runoff + tid);

        // Relative column indices within the 4-float window.
        const int xm1 = max(x - 1, 0);
        const int xp1 = min(x + 1, WW - 1);
        const int rA = xm1 - xa;
        const int rB = x   - xa;
        const int rC = xp1 - xa;

        // Separable validity: mask = colflag x rowflag (rank-1).
        const float f0 = (x - 1 >= 0) ? 1.0f : 0.0f;
        const float f2 = (x + 1 < WW) ? 1.0f : 0.0f;
        const float g0 = (y - 1 >= 0) ? 1.0f : 0.0f;
        const float g2 = (y + 1 < HH) ? 1.0f : 0.0f;
        const float cnt = (1.0f + f0 + f2) * (1.0f + g0 + g2);

        const float s0 = f0 * sel4(a0, b0, rA) + sel4(a0, b0, rB) + f2 * sel4(a0, b0, rC);
        const float s1 = f0 * sel4(a1, b1, rA) + sel4(a1, b1, rB) + f2 * sel4(a1, b1, rC);
        const float s2 = f0 * sel4(a2, b2, rA) + sel4(a2, b2, rB) + f2 * sel4(a2, b2, rC);

        const float sum  = g0 * s0 + s1 + g2 * s2;
        const float avg  = sum / cnt;
        const float diff = avg - ro;
        per_station = diff * diff;
    }

    // Deterministic block reduction: warp shuffle then shared-mem tree.
    __shared__ float smem[THREADS / 32];
    float v = per_station;
    #pragma unroll
    for (int off = 16; off > 0; off >>= 1)
        v += __shfl_down_sync(0xFFFFFFFFu, v, off);
    const int lane = threadIdx.x & 31;
    const int warp = threadIdx.x >> 5;
    if (lane == 0) smem[warp] = v;
    __syncthreads();
    if (warp == 0) {
        v = (lane < THREADS / 32) ? smem[lane] : 0.0f;
        #pragma unroll
        for (int off = 16; off > 0; off >>= 1)
            v += __shfl_down_sync(0xFFFFFFFFu, v, off);
        if (lane == 0) g_partials[blockIdx.x] = v;
    }
}

__global__ __launch_bounds__(512)
void final_reduce_kernel(float* __restrict__ out)
{
    __shared__ float smem[512 / 32];
    float s = 0.0f;
    for (int i = threadIdx.x; i < NBLK; i += 512)
        s += g_partials[i];
    #pragma unroll
    for (int off = 16; off > 0; off >>= 1)
        s += __shfl_down_sync(0xFFFFFFFFu, s, off);
    const int lane = threadIdx.x & 31;
    const int warp = threadIdx.x >> 5;
    if (lane == 0) smem[warp] = s;
    __syncthreads();
    if (warp == 0) {
        s = (lane < 512 / 32) ? smem[lane] : 0.0f;
        #pragma unroll
        for (int off = 16; off > 0; off >>= 1)
            s += __shfl_down_sync(0xFFFFFFFFu, s, off);
        if (lane == 0) out[0] = s / (float)NST;
    }
}

extern "C" void kernel_launch(void* const* d_in, const int* in_sizes, int n_in,
                              void* d_out, int out_size)
{
    const float* pred   = (const float*)d_in[0];  // (16,1,2048,2048) f32
    const int*   pos    = (const int*)  d_in[1];  // (16,5000,2) i32
    const float* runoff = (const float*)d_in[2];  // (16,5000) f32
    float* out = (float*)d_out;

    station_loss_kernel<<<NBLK, THREADS>>>(pred, pos, runoff);
    final_reduce_kernel<<<1, 512>>>(out);
}